// round 1
// baseline (speedup 1.0000x reference)
#include <cuda_runtime.h>

#define MULD 32
#define NPB 16          // nodes per block
#define THREADS 256

// SMEM layout (dynamic, 40KB total):
//   wA : float2[32][32]  (W3_0e[ij,k], W3_0e[1024+ij,k])   8KB   offset 0
//   wB : float2[32][32]  (W3_1o[ij,k], W3_1o[1024+ij,k])   8KB   offset 8KB
//   wC : float2[32][32]  (W3_1e[ij,k], W3_2e[ij,k])        8KB   offset 16KB
//   Ash: float4[16][32]  (s1, v1x, v1y, v1z) per node/i    8KB   offset 24KB
//   Bsh: float4[16][32]  (s2, v2x, v2y, v2z) per node/j    8KB   offset 32KB
// xs (prologue only) overlays wA/wB region: float[16][128]  8KB

__global__ __launch_bounds__(THREADS)
void td_kernel(const float* __restrict__ x,
               const float* __restrict__ W1_0, const float* __restrict__ W1_1,
               const float* __restrict__ W2_0, const float* __restrict__ W2_1,
               const float* __restrict__ W3_0e, const float* __restrict__ W3_1o,
               const float* __restrict__ W3_1e, const float* __restrict__ W3_2e,
               float* __restrict__ out, int N)
{
    extern __shared__ float smem[];
    float2* wA = (float2*)smem;                 // [1024]
    float2* wB = wA + 1024;                     // [1024]
    float2* wC = wB + 1024;                     // [1024]
    float4* Ash = (float4*)(wC + 1024);         // [512]
    float4* Bsh = Ash + NPB * 32;               // [512]
    float*  xs  = smem;                         // prologue overlay [16*128]

    const int tid = threadIdx.x;
    const int n0  = blockIdx.x * NPB;

    // ---- stage x rows into SMEM ----
    for (int e = tid; e < NPB * 128; e += THREADS) {
        int node = e >> 7;
        xs[e] = (n0 + node < N) ? x[(size_t)(n0 + node) * 128 + (e & 127)] : 0.0f;
    }
    __syncthreads();

    // ---- prologue: A = (s@W1_0, v@W1_1), B = (s@W2_0, v@W2_1) ----
    for (int t = tid; t < NPB * 32 * 2; t += THREADS) {
        int which = (t >= NPB * 32);            // 0: A, 1: B
        int tt = t & (NPB * 32 - 1);
        int node = tt >> 5, i = tt & 31;
        const float* Ws = which ? W2_0 : W1_0;
        const float* Wv = which ? W2_1 : W1_1;
        const float* xr = xs + node * 128;
        float s = 0.f, v0 = 0.f, v1 = 0.f, v2 = 0.f;
        #pragma unroll
        for (int m = 0; m < 32; ++m) {
            float ws = Ws[m * 32 + i];
            float wv = Wv[m * 32 + i];
            s  += xr[m] * ws;
            v0 += xr[32 + 3 * m + 0] * wv;
            v1 += xr[32 + 3 * m + 1] * wv;
            v2 += xr[32 + 3 * m + 2] * wv;
        }
        float4 r = make_float4(s, v0, v1, v2);
        if (which) Bsh[node * 32 + i] = r;
        else       Ash[node * 32 + i] = r;
    }
    __syncthreads();

    const int wid = tid >> 5;
    const int k   = tid & 31;
    const int nA  = wid * 2;
    const int nB  = wid * 2 + 1;

    float acc[2][13];
    #pragma unroll
    for (int a = 0; a < 2; ++a)
        #pragma unroll
        for (int q = 0; q < 13; ++q) acc[a][q] = 0.f;

    // ---- main loop over i (one i = one weight chunk of 32 ij values) ----
    for (int i = 0; i < 32; ++i) {
        __syncthreads();   // previous chunk consumed by all warps
        // cooperative weight chunk load: ij in [i*32, i*32+32), all k
        {
            int e = tid;                         // 1024 elems, 256 threads -> 4 iters
            #pragma unroll
            for (int r = 0; r < 4; ++r, e += THREADS) {
                int g = (i * 32 + (e >> 5)) * 32 + (e & 31);
                wA[e] = make_float2(W3_0e[g], W3_0e[32768 + g]);
                wB[e] = make_float2(W3_1o[g], W3_1o[32768 + g]);
                wC[e] = make_float2(W3_1e[g], W3_2e[g]);
            }
        }
        __syncthreads();

        float mA[14], mB[14];
        #pragma unroll
        for (int q = 0; q < 14; ++q) { mA[q] = 0.f; mB[q] = 0.f; }

        #pragma unroll 8
        for (int j = 0; j < 32; ++j) {
            const int idx = j * 32 + k;
            float2 w0 = wA[idx];
            float2 w1 = wB[idx];
            float2 w2 = wC[idx];
            float4 b0 = Bsh[nA * 32 + j];
            float4 b1 = Bsh[nB * 32 + j];
            // node A moments
            mA[0]  += w0.x * b0.x;
            mA[1]  += w0.y * b0.y;  mA[2]  += w0.y * b0.z;  mA[3]  += w0.y * b0.w;
            mA[4]  += w1.x * b0.y;  mA[5]  += w1.x * b0.z;  mA[6]  += w1.x * b0.w;
            mA[7]  += w1.y * b0.x;
            mA[8]  += w2.x * b0.y;  mA[9]  += w2.x * b0.z;  mA[10] += w2.x * b0.w;
            mA[11] += w2.y * b0.y;  mA[12] += w2.y * b0.z;  mA[13] += w2.y * b0.w;
            // node B moments
            mB[0]  += w0.x * b1.x;
            mB[1]  += w0.y * b1.y;  mB[2]  += w0.y * b1.z;  mB[3]  += w0.y * b1.w;
            mB[4]  += w1.x * b1.y;  mB[5]  += w1.x * b1.z;  mB[6]  += w1.x * b1.w;
            mB[7]  += w1.y * b1.x;
            mB[8]  += w2.x * b1.y;  mB[9]  += w2.x * b1.z;  mB[10] += w2.x * b1.w;
            mB[11] += w2.y * b1.y;  mB[12] += w2.y * b1.z;  mB[13] += w2.y * b1.w;
        }

        // ---- fold with A_i ----
        {
            float4 a0 = Ash[nA * 32 + i];
            acc[0][0]  += a0.x * mA[0];
            acc[0][1]  += a0.y * mA[1]  + a0.z * mA[2]  + a0.w * mA[3];
            acc[0][2]  += a0.x * mA[4]  + a0.y * mA[7];
            acc[0][3]  += a0.x * mA[5]  + a0.z * mA[7];
            acc[0][4]  += a0.x * mA[6]  + a0.w * mA[7];
            acc[0][5]  += a0.z * mA[10] - a0.w * mA[9];
            acc[0][6]  += a0.w * mA[8]  - a0.y * mA[10];
            acc[0][7]  += a0.y * mA[9]  - a0.z * mA[8];
            acc[0][8]  += a0.y * mA[13] + a0.w * mA[11];
            acc[0][9]  += a0.y * mA[12] + a0.z * mA[11];
            acc[0][10] += 2.f * a0.z * mA[12] - a0.y * mA[11] - a0.w * mA[13];
            acc[0][11] += a0.z * mA[13] + a0.w * mA[12];
            acc[0][12] += a0.w * mA[13] - a0.y * mA[11];
        }
        {
            float4 a1 = Ash[nB * 32 + i];
            acc[1][0]  += a1.x * mB[0];
            acc[1][1]  += a1.y * mB[1]  + a1.z * mB[2]  + a1.w * mB[3];
            acc[1][2]  += a1.x * mB[4]  + a1.y * mB[7];
            acc[1][3]  += a1.x * mB[5]  + a1.z * mB[7];
            acc[1][4]  += a1.x * mB[6]  + a1.w * mB[7];
            acc[1][5]  += a1.z * mB[10] - a1.w * mB[9];
            acc[1][6]  += a1.w * mB[8]  - a1.y * mB[10];
            acc[1][7]  += a1.y * mB[9]  - a1.z * mB[8];
            acc[1][8]  += a1.y * mB[13] + a1.w * mB[11];
            acc[1][9]  += a1.y * mB[12] + a1.z * mB[11];
            acc[1][10] += 2.f * a1.z * mB[12] - a1.y * mB[11] - a1.w * mB[13];
            acc[1][11] += a1.z * mB[13] + a1.w * mB[12];
            acc[1][12] += a1.w * mB[13] - a1.y * mB[11];
        }
    }

    // ---- write outputs: [out0(32) | out1o(32*3) | out1e(32*3) | out2e(32*5)] ----
    const float C0  = -0.57735026918962576f;  // -1/sqrt(3)
    const float C1  = -0.70710678118654752f;  // -1/sqrt(2)
    const float C2  =  0.70710678118654752f;  //  1/sqrt(2)
    const float C2z =  0.40824829046386302f;  //  1/sqrt(6)

    #pragma unroll
    for (int a = 0; a < 2; ++a) {
        int node = n0 + nA + a;
        if (node >= N) continue;
        float* o = out + (size_t)node * 384;
        const float* c = acc[a];
        o[k] = c[0] + C0 * c[1];
        o[32  + 3 * k + 0] = c[2];
        o[32  + 3 * k + 1] = c[3];
        o[32  + 3 * k + 2] = c[4];
        o[128 + 3 * k + 0] = C1 * c[5];
        o[128 + 3 * k + 1] = C1 * c[6];
        o[128 + 3 * k + 2] = C1 * c[7];
        o[224 + 5 * k + 0] = C2 * c[8];
        o[224 + 5 * k + 1] = C2 * c[9];
        o[224 + 5 * k + 2] = C2z * c[10];
        o[224 + 5 * k + 3] = C2 * c[11];
        o[224 + 5 * k + 4] = C2 * c[12];
    }
}

extern "C" void kernel_launch(void* const* d_in, const int* in_sizes, int n_in,
                              void* d_out, int out_size)
{
    const float* x     = (const float*)d_in[0];
    const float* W1_0  = (const float*)d_in[1];
    const float* W1_1  = (const float*)d_in[2];
    const float* W2_0  = (const float*)d_in[3];
    const float* W2_1  = (const float*)d_in[4];
    const float* W3_0e = (const float*)d_in[5];
    const float* W3_1o = (const float*)d_in[6];
    const float* W3_1e = (const float*)d_in[7];
    const float* W3_2e = (const float*)d_in[8];

    int N = in_sizes[0] / (4 * MULD);
    int blocks = (N + NPB - 1) / NPB;
    size_t smem = 3 * 1024 * sizeof(float2) + 2 * NPB * 32 * sizeof(float4); // 40KB

    td_kernel<<<blocks, THREADS, smem>>>(x, W1_0, W1_1, W2_0, W2_1,
                                         W3_0e, W3_1o, W3_1e, W3_2e,
                                         (float*)d_out, N);
}

// round 2
// speedup vs baseline: 1.0765x; 1.0765x over previous
#include <cuda_runtime.h>

#define MULD 32
#define NPB 16          // nodes per block
#define THREADS 256

// SMEM (dynamic, 40KB):
//   wAB: float4[1024] = (w0x, w0y, w1y, w1x) per (j,k)   16KB  @0
//   wC : float2[1024] = (w2x, w2y)           per (j,k)    8KB  @16KB
//   Ash: float4[16][32] (s1, v1x, v1y, v1z)               8KB  @24KB
//   Bsh: float4[16][32] (s2, v2x, v2y, v2z)               8KB  @32KB
//   xs (prologue) overlays wAB: float[16][128]             8KB

typedef unsigned long long u64;

__device__ __forceinline__ u64 pk(float lo, float hi) {
    u64 r; asm("mov.b64 %0, {%1, %2};" : "=l"(r) : "f"(lo), "f"(hi)); return r;
}
__device__ __forceinline__ void fma2(u64& d, u64 a, u64 b) {
    asm("fma.rn.f32x2 %0, %1, %2, %0;" : "+l"(d) : "l"(a), "l"(b));
}
__device__ __forceinline__ float2 up(u64 v) {
    float2 r; asm("mov.b64 {%0, %1}, %2;" : "=f"(r.x), "=f"(r.y) : "l"(v)); return r;
}

__global__ __launch_bounds__(THREADS)
void td_kernel(const float* __restrict__ x,
               const float* __restrict__ W1_0, const float* __restrict__ W1_1,
               const float* __restrict__ W2_0, const float* __restrict__ W2_1,
               const float* __restrict__ W3_0e, const float* __restrict__ W3_1o,
               const float* __restrict__ W3_1e, const float* __restrict__ W3_2e,
               float* __restrict__ out, int N)
{
    extern __shared__ float smem[];
    float4* wAB = (float4*)smem;                // [1024] 16KB
    float2* wC  = (float2*)(wAB + 1024);        // [1024]  8KB
    float4* Ash = (float4*)(wC + 1024);         // [512]   8KB
    float4* Bsh = Ash + NPB * 32;               // [512]   8KB
    float*  xs  = smem;                         // prologue overlay

    const int tid = threadIdx.x;
    const int n0  = blockIdx.x * NPB;

    // ---- stage x rows ----
    for (int e = tid; e < NPB * 128; e += THREADS) {
        int node = e >> 7;
        xs[e] = (n0 + node < N) ? x[(size_t)(n0 + node) * 128 + (e & 127)] : 0.0f;
    }
    __syncthreads();

    // ---- prologue: A=(s@W1_0, v@W1_1), B=(s@W2_0, v@W2_1) ----
    for (int t = tid; t < NPB * 32 * 2; t += THREADS) {
        int which = (t >= NPB * 32);
        int tt = t & (NPB * 32 - 1);
        int node = tt >> 5, i = tt & 31;
        const float* Ws = which ? W2_0 : W1_0;
        const float* Wv = which ? W2_1 : W1_1;
        const float* xr = xs + node * 128;
        float s = 0.f, v0 = 0.f, v1 = 0.f, v2 = 0.f;
        #pragma unroll
        for (int m = 0; m < 32; ++m) {
            float ws = Ws[m * 32 + i];
            float wv = Wv[m * 32 + i];
            s  += xr[m] * ws;
            v0 += xr[32 + 3 * m + 0] * wv;
            v1 += xr[32 + 3 * m + 1] * wv;
            v2 += xr[32 + 3 * m + 2] * wv;
        }
        float4 r = make_float4(s, v0, v1, v2);
        if (which) Bsh[node * 32 + i] = r;
        else       Ash[node * 32 + i] = r;
    }
    __syncthreads();

    const int wid = tid >> 5;
    const int k   = tid & 31;
    const int nA  = wid * 2;
    const int nB  = wid * 2 + 1;

    float acc[2][13];
    #pragma unroll
    for (int a = 0; a < 2; ++a)
        #pragma unroll
        for (int q = 0; q < 13; ++q) acc[a][q] = 0.f;

    for (int i = 0; i < 32; ++i) {
        __syncthreads();
        {   // cooperative weight chunk load (32 j x 32 k)
            int e = tid;
            #pragma unroll
            for (int r = 0; r < 4; ++r, e += THREADS) {
                int g = (i * 32 + (e >> 5)) * 32 + (e & 31);
                wAB[e] = make_float4(W3_0e[g], W3_0e[32768 + g],
                                     W3_1o[32768 + g], W3_1o[g]);
                wC[e]  = make_float2(W3_1e[g], W3_2e[g]);
            }
        }
        __syncthreads();

        // packed moments: per node 6 f32x2 + 2 scalar
        u64 MA0=0, MA1=0, MA2=0, MA3=0, MA4=0, MA5=0;
        u64 MB0=0, MB1=0, MB2=0, MB3=0, MB4=0, MB5=0;
        float mA8 = 0.f, mA11 = 0.f, mB8 = 0.f, mB11 = 0.f;

        const float4* BA = Bsh + nA * 32;
        const float4* BB = Bsh + nB * 32;

        #pragma unroll 8
        for (int j = 0; j < 32; ++j) {
            const int idx = j * 32 + k;
            ulonglong2 w01 = *(const ulonglong2*)&wAB[idx]; // P1=(w0x,w0y), P3=(w1y,w1x)
            float2 cf = wC[idx];                            // (w2x, w2y)
            float2 p1f = up(w01.x);
            float2 p3f = up(w01.y);
            u64 P2  = pk(p1f.y, p1f.y);   // (w0y, w0y)
            u64 P4  = pk(p3f.y, p3f.y);   // (w1x, w1x)
            u64 S2x = pk(cf.x, cf.x);
            u64 S2y = pk(cf.y, cf.y);

            ulonglong2 ba = *(const ulonglong2*)&BA[j];     // (bx,by),(bz,bw)
            fma2(MA0, w01.x, ba.x);   // (w0x*bx, w0y*by)
            fma2(MA1, P2,    ba.y);   // (w0y*bz, w0y*bw)
            fma2(MA2, w01.y, ba.x);   // (w1y*bx, w1x*by)
            fma2(MA3, P4,    ba.y);   // (w1x*bz, w1x*bw)
            fma2(MA4, S2x,   ba.y);   // (w2x*bz, w2x*bw)
            fma2(MA5, S2y,   ba.y);   // (w2y*bz, w2y*bw)
            float2 baxy = up(ba.x);
            mA8  += cf.x * baxy.y;    // w2x*by
            mA11 += cf.y * baxy.y;    // w2y*by

            ulonglong2 bb = *(const ulonglong2*)&BB[j];
            fma2(MB0, w01.x, bb.x);
            fma2(MB1, P2,    bb.y);
            fma2(MB2, w01.y, bb.x);
            fma2(MB3, P4,    bb.y);
            fma2(MB4, S2x,   bb.y);
            fma2(MB5, S2y,   bb.y);
            float2 bbxy = up(bb.x);
            mB8  += cf.x * bbxy.y;
            mB11 += cf.y * bbxy.y;
        }

        // ---- fold with A_i ----
        {
            float4 a0 = Ash[nA * 32 + i];
            float2 u0 = up(MA0), u1 = up(MA1), u2 = up(MA2),
                   u3 = up(MA3), u4 = up(MA4), u5 = up(MA5);
            float m0 = u0.x, m1 = u0.y, m2 = u1.x, m3 = u1.y;
            float m7 = u2.x, m4 = u2.y, m5 = u3.x, m6 = u3.y;
            float m9 = u4.x, m10 = u4.y, m12 = u5.x, m13 = u5.y;
            float m8 = mA8, m11 = mA11;
            acc[0][0]  += a0.x * m0;
            acc[0][1]  += a0.y * m1  + a0.z * m2  + a0.w * m3;
            acc[0][2]  += a0.x * m4  + a0.y * m7;
            acc[0][3]  += a0.x * m5  + a0.z * m7;
            acc[0][4]  += a0.x * m6  + a0.w * m7;
            acc[0][5]  += a0.z * m10 - a0.w * m9;
            acc[0][6]  += a0.w * m8  - a0.y * m10;
            acc[0][7]  += a0.y * m9  - a0.z * m8;
            acc[0][8]  += a0.y * m13 + a0.w * m11;
            acc[0][9]  += a0.y * m12 + a0.z * m11;
            acc[0][10] += 2.f * a0.z * m12 - a0.y * m11 - a0.w * m13;
            acc[0][11] += a0.z * m13 + a0.w * m12;
            acc[0][12] += a0.w * m13 - a0.y * m11;
        }
        {
            float4 a1 = Ash[nB * 32 + i];
            float2 u0 = up(MB0), u1 = up(MB1), u2 = up(MB2),
                   u3 = up(MB3), u4 = up(MB4), u5 = up(MB5);
            float m0 = u0.x, m1 = u0.y, m2 = u1.x, m3 = u1.y;
            float m7 = u2.x, m4 = u2.y, m5 = u3.x, m6 = u3.y;
            float m9 = u4.x, m10 = u4.y, m12 = u5.x, m13 = u5.y;
            float m8 = mB8, m11 = mB11;
            acc[1][0]  += a1.x * m0;
            acc[1][1]  += a1.y * m1  + a1.z * m2  + a1.w * m3;
            acc[1][2]  += a1.x * m4  + a1.y * m7;
            acc[1][3]  += a1.x * m5  + a1.z * m7;
            acc[1][4]  += a1.x * m6  + a1.w * m7;
            acc[1][5]  += a1.z * m10 - a1.w * m9;
            acc[1][6]  += a1.w * m8  - a1.y * m10;
            acc[1][7]  += a1.y * m9  - a1.z * m8;
            acc[1][8]  += a1.y * m13 + a1.w * m11;
            acc[1][9]  += a1.y * m12 + a1.z * m11;
            acc[1][10] += 2.f * a1.z * m12 - a1.y * m11 - a1.w * m13;
            acc[1][11] += a1.z * m13 + a1.w * m12;
            acc[1][12] += a1.w * m13 - a1.y * m11;
        }
    }

    // ---- outputs ----
    const float C0  = -0.57735026918962576f;
    const float C1  = -0.70710678118654752f;
    const float C2  =  0.70710678118654752f;
    const float C2z =  0.40824829046386302f;

    #pragma unroll
    for (int a = 0; a < 2; ++a) {
        int node = n0 + nA + a;
        if (node >= N) continue;
        float* o = out + (size_t)node * 384;
        const float* c = acc[a];
        o[k] = c[0] + C0 * c[1];
        o[32  + 3 * k + 0] = c[2];
        o[32  + 3 * k + 1] = c[3];
        o[32  + 3 * k + 2] = c[4];
        o[128 + 3 * k + 0] = C1 * c[5];
        o[128 + 3 * k + 1] = C1 * c[6];
        o[128 + 3 * k + 2] = C1 * c[7];
        o[224 + 5 * k + 0] = C2 * c[8];
        o[224 + 5 * k + 1] = C2 * c[9];
        o[224 + 5 * k + 2] = C2z * c[10];
        o[224 + 5 * k + 3] = C2 * c[11];
        o[224 + 5 * k + 4] = C2 * c[12];
    }
}

extern "C" void kernel_launch(void* const* d_in, const int* in_sizes, int n_in,
                              void* d_out, int out_size)
{
    const float* x     = (const float*)d_in[0];
    const float* W1_0  = (const float*)d_in[1];
    const float* W1_1  = (const float*)d_in[2];
    const float* W2_0  = (const float*)d_in[3];
    const float* W2_1  = (const float*)d_in[4];
    const float* W3_0e = (const float*)d_in[5];
    const float* W3_1o = (const float*)d_in[6];
    const float* W3_1e = (const float*)d_in[7];
    const float* W3_2e = (const float*)d_in[8];

    int N = in_sizes[0] / (4 * MULD);
    int blocks = (N + NPB - 1) / NPB;
    size_t smem = 1024 * sizeof(float4) + 1024 * sizeof(float2)
                + 2 * NPB * 32 * sizeof(float4); // 40KB

    td_kernel<<<blocks, THREADS, smem>>>(x, W1_0, W1_1, W2_0, W2_1,
                                         W3_0e, W3_1o, W3_1e, W3_2e,
                                         (float*)d_out, N);
}